// round 16
// baseline (speedup 1.0000x reference)
#include <cuda_runtime.h>
#include <cstdint>
#include <cstddef>

#define NN 100000
#define NE 3200000
#define SCAN_T 1024
#define SCAN_NB ((NN + SCAN_T - 1) / SCAN_T)

// ---------------- static scratch (no runtime allocation allowed) ----------------
__device__ __align__(128) int   g_deg[NN];          // degree (by src); reused as fill cursor
__device__ __align__(128) int   g_cnt[NN];          // dst histogram
__device__ __align__(128) int   g_incl[NN];         // scan temp
__device__ __align__(128) int   g_bsums[SCAN_NB + 8];
__device__ __align__(128) int   g_rowptr[NN + 1];
__device__ __align__(128) int   g_col[NE];
__device__ __align__(128) float g_val[NE];
__device__ __align__(128) float g_dis[NN];

__device__ __align__(128) float g_T1[(size_t)NN * 512];
__device__ __align__(128) float g_T2[(size_t)NN * 512];
__device__ __align__(128) float g_H1[(size_t)NN * 256];
__device__ __align__(128) float g_H2[(size_t)NN * 512];

__device__ __align__(128) float g_Wp1[3 * 128 * 256];
__device__ __align__(128) float g_Wp2[3 * 256 * 512];
__device__ __align__(128) float g_Wp3[3 * 512 * 1024];
__device__ __align__(128) float g_bp1[256];
__device__ __align__(128) float g_bp2[512];
__device__ __align__(128) float g_bp3[1024];

// ---------------- small helper kernels ----------------
__global__ void k_zero2(void) {
    int i = blockIdx.x * blockDim.x + threadIdx.x;
    if (i < NN) { g_deg[i] = 0; g_cnt[i] = 0; }
}
__global__ void k_zero_deg(void) {
    int i = blockIdx.x * blockDim.x + threadIdx.x;
    if (i < NN) g_deg[i] = 0;
}
__global__ void k_hist(const int* __restrict__ src, const int* __restrict__ dst) {
    int e = blockIdx.x * blockDim.x + threadIdx.x;
    if (e < NE) {
        atomicAdd(&g_deg[src[e]], 1);
        atomicAdd(&g_cnt[dst[e]], 1);
    }
}
__global__ void k_dis(void) {
    int i = blockIdx.x * blockDim.x + threadIdx.x;
    if (i < NN) {
        int d = g_deg[i];
        g_dis[i] = (d > 0) ? rsqrtf((float)d) : 0.0f;
    }
}
// block-wise inclusive scan of g_cnt
__global__ void k_scan_block(void) {
    __shared__ int s[SCAN_T];
    int tid = threadIdx.x;
    int i = blockIdx.x * SCAN_T + tid;
    int v = (i < NN) ? g_cnt[i] : 0;
    s[tid] = v;
    __syncthreads();
    for (int off = 1; off < SCAN_T; off <<= 1) {
        int t = 0;
        if (tid >= off) t = s[tid - off];
        __syncthreads();
        v += t;
        s[tid] = v;
        __syncthreads();
    }
    if (i < NN) g_incl[i] = v;
    if (tid == SCAN_T - 1) g_bsums[blockIdx.x] = v;
}
__global__ void k_scan_sums(void) {
    if (blockIdx.x == 0 && threadIdx.x == 0) {
        int acc = 0;
        for (int b = 0; b < SCAN_NB; b++) { int t = g_bsums[b]; g_bsums[b] = acc; acc += t; }
    }
}
__global__ void k_finalize(void) {
    int i = blockIdx.x * SCAN_T + threadIdx.x;
    if (i < NN) g_rowptr[i] = g_incl[i] - g_cnt[i] + g_bsums[blockIdx.x];
    if (i == 0) g_rowptr[NN] = NE;
}
__global__ void k_fill(const int* __restrict__ src, const int* __restrict__ dst) {
    int e = blockIdx.x * blockDim.x + threadIdx.x;
    if (e < NE) {
        int s = src[e], d = dst[e];
        int pos = g_rowptr[d] + atomicAdd(&g_deg[d], 1);
        g_col[pos] = s;
        g_val[pos] = -g_dis[s] * g_dis[d];
    }
}
__global__ void k_pack_w(const float* __restrict__ W, float* __restrict__ Wp,
                         int Kin, int Nin, int Kpad, int Npad) {
    long idx = blockIdx.x * (long)blockDim.x + threadIdx.x;
    long total = 3L * Kpad * Npad;
    if (idx >= total) return;
    int n = (int)(idx % Npad);
    long r = idx / Npad;
    int k = (int)(r % Kpad);
    int m = (int)(r / Kpad);
    float v = 0.0f;
    if (k < Kin && n < Nin) v = W[((long)m * Kin + k) * Nin + n];
    Wp[idx] = v;
}
__global__ void k_pack_b(const float* __restrict__ b, float* __restrict__ bp, int Nin, int Npad) {
    int i = blockIdx.x * blockDim.x + threadIdx.x;
    if (i < Npad) bp[i] = (i < Nin) ? b[i] : 0.0f;
}

// ---------------- SpMM: O[r,:] = sum_e val[e] * H[col[e],:]   (CSR by dst) ----------------
// fused==1: O[r,:] = 2*acc - Hprev[r,:]   (Chebyshev T2)
__global__ void k_spmm(const float* __restrict__ H, int ld, float* __restrict__ O,
                       const float* __restrict__ Hprev, int fused) {
    int r = blockIdx.x;
    int f = blockIdx.y * 128 + threadIdx.x;
    int e0 = g_rowptr[r], e1 = g_rowptr[r + 1];
    float acc = 0.0f;
    int e = e0;
    for (; e + 4 <= e1; e += 4) {
        int   c0 = g_col[e], c1 = g_col[e + 1], c2 = g_col[e + 2], c3 = g_col[e + 3];
        float v0 = g_val[e], v1 = g_val[e + 1], v2 = g_val[e + 2], v3 = g_val[e + 3];
        float h0 = H[(size_t)c0 * ld + f];
        float h1 = H[(size_t)c1 * ld + f];
        float h2 = H[(size_t)c2 * ld + f];
        float h3 = H[(size_t)c3 * ld + f];
        acc += v0 * h0;
        acc += v1 * h1;
        acc += v2 * h2;
        acc += v3 * h3;
    }
    for (; e < e1; ++e) acc += g_val[e] * H[(size_t)g_col[e] * ld + f];
    size_t o = (size_t)r * ld + f;
    O[o] = fused ? (2.0f * acc - Hprev[o]) : acc;
}

// ---------------- tf32 GEMM: C = relu(A0@B0 + A1@B1 + A2@B2 + bias) ----------------
// A_m: [M, KPAD] row-major, ldA = KPAD. Bw: [3][KPAD][Npad] row-major (padded, zero-filled).
// Block tile 128x128x32, 256 threads, 8 warps as 2(M)x4(N), warp tile 64x32 via m16n8k8.
__device__ __forceinline__ uint32_t f2tf32(float x) {
    uint32_t u;
    asm("cvt.rna.tf32.f32 %0, %1;" : "=r"(u) : "f"(x));
    return u;
}

template <int KPAD>
__global__ __launch_bounds__(256, 1)
void gemm3_tf32(const float* __restrict__ A0, const float* __restrict__ A1,
                const float* __restrict__ A2, const float* __restrict__ Bw,
                int Npad, const float* __restrict__ bias,
                float* __restrict__ C, int ldC, int Ncols, int M) {
    __shared__ __align__(16) uint32_t As[128][36];  // [row][k], stride 36 -> conflict-free frag loads
    __shared__ __align__(16) uint32_t Bs[32][136];  // [k][n],  stride 136 -> conflict-free frag loads

    const int tid  = threadIdx.x;
    const int lane = tid & 31;
    const int warp = tid >> 5;
    const int wm = warp >> 2;   // 0..1
    const int wn = warp & 3;    // 0..3
    const int g  = lane >> 2;   // 0..7
    const int t  = lane & 3;    // 0..3

    const int bm = blockIdx.y * 128;
    const int bn = blockIdx.x * 128;

    float acc[4][4][4];
#pragma unroll
    for (int i = 0; i < 4; i++)
#pragma unroll
        for (int j = 0; j < 4; j++)
#pragma unroll
            for (int q = 0; q < 4; q++) acc[i][j][q] = 0.0f;

    const int ktiles = (3 * KPAD) >> 5;

    // global load mapping
    const int arow = tid >> 3;         // 0..31 (A row within 32-row pass)
    const int acol = (tid & 7) * 4;    // 0..28 (A k offset)
    const int brow = warp;             // 0..7  (B k row within 8-row pass)
    const int bcol = (lane) * 4;       // 0..124 (B n offset); lane = tid&31

    float4 ra[4], rb[4];

    auto loadTile = [&](int kt) {
        int kglob = kt << 5;
        int m  = kglob / KPAD;         // BK=32 divides KPAD, tile never crosses matrices
        int kl = kglob - m * KPAD;
        const float* A = (m == 0) ? A0 : ((m == 1) ? A1 : A2);
        const float* B = Bw + (size_t)m * KPAD * Npad;
#pragma unroll
        for (int p = 0; p < 4; p++) {
            int r = bm + p * 32 + arow;
            if (r < M)
                ra[p] = *reinterpret_cast<const float4*>(A + (size_t)r * KPAD + kl + acol);
            else
                ra[p] = make_float4(0.f, 0.f, 0.f, 0.f);
        }
#pragma unroll
        for (int p = 0; p < 4; p++) {
            int kr = kl + p * 8 + brow;
            rb[p] = *reinterpret_cast<const float4*>(B + (size_t)kr * Npad + bn + bcol);
        }
    };

    auto storeTile = [&]() {
#pragma unroll
        for (int p = 0; p < 4; p++) {
            int r = p * 32 + arow;
            uint4 u;
            u.x = f2tf32(ra[p].x); u.y = f2tf32(ra[p].y);
            u.z = f2tf32(ra[p].z); u.w = f2tf32(ra[p].w);
            *reinterpret_cast<uint4*>(&As[r][acol]) = u;
        }
#pragma unroll
        for (int p = 0; p < 4; p++) {
            int kr = p * 8 + brow;
            uint4 u;
            u.x = f2tf32(rb[p].x); u.y = f2tf32(rb[p].y);
            u.z = f2tf32(rb[p].z); u.w = f2tf32(rb[p].w);
            *reinterpret_cast<uint4*>(&Bs[kr][bcol]) = u;
        }
    };

    loadTile(0);
    for (int kt = 0; kt < ktiles; ++kt) {
        __syncthreads();
        storeTile();
        __syncthreads();
        if (kt + 1 < ktiles) loadTile(kt + 1);

#pragma unroll
        for (int kk = 0; kk < 4; ++kk) {
            const int k0 = kk * 8;
            uint32_t af[4][4], bf[4][2];
#pragma unroll
            for (int mi = 0; mi < 4; ++mi) {
                int rb_ = wm * 64 + mi * 16 + g;
                af[mi][0] = As[rb_][k0 + t];
                af[mi][1] = As[rb_ + 8][k0 + t];
                af[mi][2] = As[rb_][k0 + t + 4];
                af[mi][3] = As[rb_ + 8][k0 + t + 4];
            }
#pragma unroll
            for (int ni = 0; ni < 4; ++ni) {
                int cb = wn * 32 + ni * 8 + g;
                bf[ni][0] = Bs[k0 + t][cb];
                bf[ni][1] = Bs[k0 + t + 4][cb];
            }
#pragma unroll
            for (int mi = 0; mi < 4; ++mi)
#pragma unroll
                for (int ni = 0; ni < 4; ++ni)
                    asm volatile(
                        "mma.sync.aligned.m16n8k8.row.col.f32.tf32.tf32.f32 "
                        "{%0,%1,%2,%3}, {%4,%5,%6,%7}, {%8,%9}, {%0,%1,%2,%3};\n"
                        : "+f"(acc[mi][ni][0]), "+f"(acc[mi][ni][1]),
                          "+f"(acc[mi][ni][2]), "+f"(acc[mi][ni][3])
                        : "r"(af[mi][0]), "r"(af[mi][1]), "r"(af[mi][2]), "r"(af[mi][3]),
                          "r"(bf[ni][0]), "r"(bf[ni][1]));
        }
    }

    // epilogue: bias + relu
#pragma unroll
    for (int mi = 0; mi < 4; ++mi) {
        int r0 = bm + wm * 64 + mi * 16 + g;
        int r1 = r0 + 8;
#pragma unroll
        for (int ni = 0; ni < 4; ++ni) {
            int c = bn + wn * 32 + ni * 8 + t * 2;
            if (c < Ncols) {
                float b0 = bias[c], b1 = bias[c + 1];
                if (r0 < M) {
                    float v0 = fmaxf(acc[mi][ni][0] + b0, 0.0f);
                    float v1 = fmaxf(acc[mi][ni][1] + b1, 0.0f);
                    *reinterpret_cast<float2*>(C + (size_t)r0 * ldC + c) = make_float2(v0, v1);
                }
                if (r1 < M) {
                    float v2 = fmaxf(acc[mi][ni][2] + b0, 0.0f);
                    float v3 = fmaxf(acc[mi][ni][3] + b1, 0.0f);
                    *reinterpret_cast<float2*>(C + (size_t)r1 * ldC + c) = make_float2(v2, v3);
                }
            }
        }
    }
}

// ---------------- launch ----------------
extern "C" void kernel_launch(void* const* d_in, const int* in_sizes, int n_in,
                              void* d_out, int out_size) {
    (void)in_sizes; (void)n_in; (void)out_size;
    const float* x  = (const float*)d_in[0];
    const int*   ei = (const int*)d_in[1];
    const float* W1 = (const float*)d_in[2];
    const float* b1 = (const float*)d_in[3];
    const float* W2 = (const float*)d_in[4];
    const float* b2 = (const float*)d_in[5];
    const float* W3 = (const float*)d_in[6];
    const float* b3 = (const float*)d_in[7];
    float* out = (float*)d_out;
    const int* src = ei;
    const int* dst = ei + NE;

    void* p;
    float *T1, *T2, *H1, *H2, *Wp1, *Wp2, *Wp3, *bp1, *bp2, *bp3;
    cudaGetSymbolAddress(&p, g_T1);  T1  = (float*)p;
    cudaGetSymbolAddress(&p, g_T2);  T2  = (float*)p;
    cudaGetSymbolAddress(&p, g_H1);  H1  = (float*)p;
    cudaGetSymbolAddress(&p, g_H2);  H2  = (float*)p;
    cudaGetSymbolAddress(&p, g_Wp1); Wp1 = (float*)p;
    cudaGetSymbolAddress(&p, g_Wp2); Wp2 = (float*)p;
    cudaGetSymbolAddress(&p, g_Wp3); Wp3 = (float*)p;
    cudaGetSymbolAddress(&p, g_bp1); bp1 = (float*)p;
    cudaGetSymbolAddress(&p, g_bp2); bp2 = (float*)p;
    cudaGetSymbolAddress(&p, g_bp3); bp3 = (float*)p;

    const int TB = 256;
    const int MB = (NN + 127) / 128;  // 782

    // --- CSR build (by dst) + degree normalization ---
    k_zero2<<<(NN + TB - 1) / TB, TB>>>();
    k_hist<<<(NE + TB - 1) / TB, TB>>>(src, dst);
    k_dis<<<(NN + TB - 1) / TB, TB>>>();
    k_scan_block<<<SCAN_NB, SCAN_T>>>();
    k_scan_sums<<<1, 32>>>();
    k_finalize<<<SCAN_NB, SCAN_T>>>();
    k_zero_deg<<<(NN + TB - 1) / TB, TB>>>();
    k_fill<<<(NE + TB - 1) / TB, TB>>>(src, dst);

    // --- pack weights/biases into padded layouts ---
    k_pack_w<<<(3 * 128 * 256  + TB - 1) / TB, TB>>>(W1, Wp1, 128, 250, 128, 256);
    k_pack_w<<<(3 * 256 * 512  + TB - 1) / TB, TB>>>(W2, Wp2, 250, 500, 256, 512);
    k_pack_w<<<(3 * 512 * 1024 + TB - 1) / TB, TB>>>(W3, Wp3, 500, 1000, 512, 1024);
    k_pack_b<<<1, 256>>>(b1, bp1, 250, 256);
    k_pack_b<<<2, 256>>>(b2, bp2, 500, 512);
    k_pack_b<<<4, 256>>>(b3, bp3, 1000, 1024);

    // --- layer 1: 128 -> 250 (pad 256) ---
    k_spmm<<<dim3(NN, 1), 128>>>(x, 128, T1, x, 0);
    k_spmm<<<dim3(NN, 1), 128>>>(T1, 128, T2, x, 1);
    gemm3_tf32<128><<<dim3(2, MB), 256>>>(x, T1, T2, Wp1, 256, bp1, H1, 256, 256, NN);

    // --- layer 2: 250 (pad 256) -> 500 (pad 512) ---
    k_spmm<<<dim3(NN, 2), 128>>>(H1, 256, T1, H1, 0);
    k_spmm<<<dim3(NN, 2), 128>>>(T1, 256, T2, H1, 1);
    gemm3_tf32<256><<<dim3(4, MB), 256>>>(H1, T1, T2, Wp2, 512, bp2, H2, 512, 512, NN);

    // --- layer 3: 500 (pad 512) -> 1000 (out, stride 1000) ---
    k_spmm<<<dim3(NN, 4), 128>>>(H2, 512, T1, H2, 0);
    k_spmm<<<dim3(NN, 4), 128>>>(T1, 512, T2, H2, 1);
    gemm3_tf32<512><<<dim3(8, MB), 256>>>(H2, T1, T2, Wp3, 1024, bp3, out, 1000, 1000, NN);
}

// round 17
// speedup vs baseline: 1.0017x; 1.0017x over previous
#include <cuda_runtime.h>
#include <cstdint>
#include <cstddef>

#define NN 100000
#define NE 3200000
#define SCAN_T 1024
#define SCAN_NB ((NN + SCAN_T - 1) / SCAN_T)

// ---------------- static scratch (no runtime allocation allowed) ----------------
__device__ __align__(128) int   g_deg[NN];          // degree (by src); reused as fill cursor
__device__ __align__(128) int   g_cnt[NN];          // dst histogram
__device__ __align__(128) int   g_incl[NN];         // scan temp
__device__ __align__(128) int   g_bsums[SCAN_NB + 8];
__device__ __align__(128) int   g_rowptr[NN + 1];
__device__ __align__(128) int   g_col[NE];
__device__ __align__(128) float g_val[NE];
__device__ __align__(128) float g_dis[NN];

__device__ __align__(128) float g_T1[(size_t)NN * 512];
__device__ __align__(128) float g_T2[(size_t)NN * 512];
__device__ __align__(128) float g_H1[(size_t)NN * 256];
__device__ __align__(128) float g_H2[(size_t)NN * 512];

__device__ __align__(128) float g_Wp1[3 * 128 * 256];
__device__ __align__(128) float g_Wp2[3 * 256 * 512];
__device__ __align__(128) float g_Wp3[3 * 512 * 1024];
__device__ __align__(128) float g_bp1[256];
__device__ __align__(128) float g_bp2[512];
__device__ __align__(128) float g_bp3[1024];

// ---------------- small helper kernels ----------------
__global__ void k_zero2(void) {
    int i = blockIdx.x * blockDim.x + threadIdx.x;
    if (i < NN) { g_deg[i] = 0; g_cnt[i] = 0; }
}
__global__ void k_zero_deg(void) {
    int i = blockIdx.x * blockDim.x + threadIdx.x;
    if (i < NN) g_deg[i] = 0;
}
__global__ void k_hist(const int* __restrict__ src, const int* __restrict__ dst) {
    int e = blockIdx.x * blockDim.x + threadIdx.x;
    if (e < NE) {
        atomicAdd(&g_deg[src[e]], 1);
        atomicAdd(&g_cnt[dst[e]], 1);
    }
}
__global__ void k_dis(void) {
    int i = blockIdx.x * blockDim.x + threadIdx.x;
    if (i < NN) {
        int d = g_deg[i];
        g_dis[i] = (d > 0) ? rsqrtf((float)d) : 0.0f;
    }
}
// block-wise inclusive scan of g_cnt
__global__ void k_scan_block(void) {
    __shared__ int s[SCAN_T];
    int tid = threadIdx.x;
    int i = blockIdx.x * SCAN_T + tid;
    int v = (i < NN) ? g_cnt[i] : 0;
    s[tid] = v;
    __syncthreads();
    for (int off = 1; off < SCAN_T; off <<= 1) {
        int t = 0;
        if (tid >= off) t = s[tid - off];
        __syncthreads();
        v += t;
        s[tid] = v;
        __syncthreads();
    }
    if (i < NN) g_incl[i] = v;
    if (tid == SCAN_T - 1) g_bsums[blockIdx.x] = v;
}
__global__ void k_scan_sums(void) {
    if (blockIdx.x == 0 && threadIdx.x == 0) {
        int acc = 0;
        for (int b = 0; b < SCAN_NB; b++) { int t = g_bsums[b]; g_bsums[b] = acc; acc += t; }
    }
}
__global__ void k_finalize(void) {
    int i = blockIdx.x * SCAN_T + threadIdx.x;
    if (i < NN) g_rowptr[i] = g_incl[i] - g_cnt[i] + g_bsums[blockIdx.x];
    if (i == 0) g_rowptr[NN] = NE;
}
__global__ void k_fill(const int* __restrict__ src, const int* __restrict__ dst) {
    int e = blockIdx.x * blockDim.x + threadIdx.x;
    if (e < NE) {
        int s = src[e], d = dst[e];
        int pos = g_rowptr[d] + atomicAdd(&g_deg[d], 1);
        g_col[pos] = s;
        g_val[pos] = -g_dis[s] * g_dis[d];
    }
}
__global__ void k_pack_w(const float* __restrict__ W, float* __restrict__ Wp,
                         int Kin, int Nin, int Kpad, int Npad) {
    long idx = blockIdx.x * (long)blockDim.x + threadIdx.x;
    long total = 3L * Kpad * Npad;
    if (idx >= total) return;
    int n = (int)(idx % Npad);
    long r = idx / Npad;
    int k = (int)(r % Kpad);
    int m = (int)(r / Kpad);
    float v = 0.0f;
    if (k < Kin && n < Nin) v = W[((long)m * Kin + k) * Nin + n];
    Wp[idx] = v;
}
__global__ void k_pack_b(const float* __restrict__ b, float* __restrict__ bp, int Nin, int Npad) {
    int i = blockIdx.x * blockDim.x + threadIdx.x;
    if (i < Npad) bp[i] = (i < Nin) ? b[i] : 0.0f;
}

// ---------------- SpMM: O[r,:] = sum_e val[e] * H[col[e],:]   (CSR by dst) ----------------
// fused==1: O[r,:] = 2*acc - Hprev[r,:]   (Chebyshev T2)
__global__ void k_spmm(const float* __restrict__ H, int ld, float* __restrict__ O,
                       const float* __restrict__ Hprev, int fused) {
    int r = blockIdx.x;
    int f = blockIdx.y * 128 + threadIdx.x;
    int e0 = g_rowptr[r], e1 = g_rowptr[r + 1];
    float acc = 0.0f;
    int e = e0;
    for (; e + 4 <= e1; e += 4) {
        int   c0 = g_col[e], c1 = g_col[e + 1], c2 = g_col[e + 2], c3 = g_col[e + 3];
        float v0 = g_val[e], v1 = g_val[e + 1], v2 = g_val[e + 2], v3 = g_val[e + 3];
        float h0 = H[(size_t)c0 * ld + f];
        float h1 = H[(size_t)c1 * ld + f];
        float h2 = H[(size_t)c2 * ld + f];
        float h3 = H[(size_t)c3 * ld + f];
        acc += v0 * h0;
        acc += v1 * h1;
        acc += v2 * h2;
        acc += v3 * h3;
    }
    for (; e < e1; ++e) acc += g_val[e] * H[(size_t)g_col[e] * ld + f];
    size_t o = (size_t)r * ld + f;
    O[o] = fused ? (2.0f * acc - Hprev[o]) : acc;
}

// ---------------- tf32 GEMM: C = relu(A0@B0 + A1@B1 + A2@B2 + bias) ----------------
// A_m: [M, KPAD] row-major, ldA = KPAD. Bw: [3][KPAD][Npad] row-major (padded, zero-filled).
// Block tile 128x128x32, 256 threads, 8 warps as 2(M)x4(N), warp tile 64x32 via m16n8k8.
__device__ __forceinline__ uint32_t f2tf32(float x) {
    uint32_t u;
    asm("cvt.rna.tf32.f32 %0, %1;" : "=r"(u) : "f"(x));
    return u;
}

template <int KPAD>
__global__ __launch_bounds__(256, 1)
void gemm3_tf32(const float* __restrict__ A0, const float* __restrict__ A1,
                const float* __restrict__ A2, const float* __restrict__ Bw,
                int Npad, const float* __restrict__ bias,
                float* __restrict__ C, int ldC, int Ncols, int M) {
    __shared__ __align__(16) uint32_t As[128][36];  // [row][k], stride 36 -> conflict-free frag loads
    __shared__ __align__(16) uint32_t Bs[32][136];  // [k][n],  stride 136 -> conflict-free frag loads

    const int tid  = threadIdx.x;
    const int lane = tid & 31;
    const int warp = tid >> 5;
    const int wm = warp >> 2;   // 0..1
    const int wn = warp & 3;    // 0..3
    const int g  = lane >> 2;   // 0..7
    const int t  = lane & 3;    // 0..3

    const int bm = blockIdx.y * 128;
    const int bn = blockIdx.x * 128;

    float acc[4][4][4];
#pragma unroll
    for (int i = 0; i < 4; i++)
#pragma unroll
        for (int j = 0; j < 4; j++)
#pragma unroll
            for (int q = 0; q < 4; q++) acc[i][j][q] = 0.0f;

    const int ktiles = (3 * KPAD) >> 5;

    // global load mapping
    const int arow = tid >> 3;         // 0..31 (A row within 32-row pass)
    const int acol = (tid & 7) * 4;    // 0..28 (A k offset)
    const int brow = warp;             // 0..7  (B k row within 8-row pass)
    const int bcol = (lane) * 4;       // 0..124 (B n offset); lane = tid&31

    float4 ra[4], rb[4];

    auto loadTile = [&](int kt) {
        int kglob = kt << 5;
        int m  = kglob / KPAD;         // BK=32 divides KPAD, tile never crosses matrices
        int kl = kglob - m * KPAD;
        const float* A = (m == 0) ? A0 : ((m == 1) ? A1 : A2);
        const float* B = Bw + (size_t)m * KPAD * Npad;
#pragma unroll
        for (int p = 0; p < 4; p++) {
            int r = bm + p * 32 + arow;
            if (r < M)
                ra[p] = *reinterpret_cast<const float4*>(A + (size_t)r * KPAD + kl + acol);
            else
                ra[p] = make_float4(0.f, 0.f, 0.f, 0.f);
        }
#pragma unroll
        for (int p = 0; p < 4; p++) {
            int kr = kl + p * 8 + brow;
            rb[p] = *reinterpret_cast<const float4*>(B + (size_t)kr * Npad + bn + bcol);
        }
    };

    auto storeTile = [&]() {
#pragma unroll
        for (int p = 0; p < 4; p++) {
            int r = p * 32 + arow;
            uint4 u;
            u.x = f2tf32(ra[p].x); u.y = f2tf32(ra[p].y);
            u.z = f2tf32(ra[p].z); u.w = f2tf32(ra[p].w);
            *reinterpret_cast<uint4*>(&As[r][acol]) = u;
        }
#pragma unroll
        for (int p = 0; p < 4; p++) {
            int kr = p * 8 + brow;
            uint4 u;
            u.x = f2tf32(rb[p].x); u.y = f2tf32(rb[p].y);
            u.z = f2tf32(rb[p].z); u.w = f2tf32(rb[p].w);
            *reinterpret_cast<uint4*>(&Bs[kr][bcol]) = u;
        }
    };

    loadTile(0);
    for (int kt = 0; kt < ktiles; ++kt) {
        __syncthreads();
        storeTile();
        __syncthreads();
        if (kt + 1 < ktiles) loadTile(kt + 1);

#pragma unroll
        for (int kk = 0; kk < 4; ++kk) {
            const int k0 = kk * 8;
            uint32_t af[4][4], bf[4][2];
#pragma unroll
            for (int mi = 0; mi < 4; ++mi) {
                int rb_ = wm * 64 + mi * 16 + g;
                af[mi][0] = As[rb_][k0 + t];
                af[mi][1] = As[rb_ + 8][k0 + t];
                af[mi][2] = As[rb_][k0 + t + 4];
                af[mi][3] = As[rb_ + 8][k0 + t + 4];
            }
#pragma unroll
            for (int ni = 0; ni < 4; ++ni) {
                int cb = wn * 32 + ni * 8 + g;
                bf[ni][0] = Bs[k0 + t][cb];
                bf[ni][1] = Bs[k0 + t + 4][cb];
            }
#pragma unroll
            for (int mi = 0; mi < 4; ++mi)
#pragma unroll
                for (int ni = 0; ni < 4; ++ni)
                    asm volatile(
                        "mma.sync.aligned.m16n8k8.row.col.f32.tf32.tf32.f32 "
                        "{%0,%1,%2,%3}, {%4,%5,%6,%7}, {%8,%9}, {%0,%1,%2,%3};\n"
                        : "+f"(acc[mi][ni][0]), "+f"(acc[mi][ni][1]),
                          "+f"(acc[mi][ni][2]), "+f"(acc[mi][ni][3])
                        : "r"(af[mi][0]), "r"(af[mi][1]), "r"(af[mi][2]), "r"(af[mi][3]),
                          "r"(bf[ni][0]), "r"(bf[ni][1]));
        }
    }

    // epilogue: bias + relu
#pragma unroll
    for (int mi = 0; mi < 4; ++mi) {
        int r0 = bm + wm * 64 + mi * 16 + g;
        int r1 = r0 + 8;
#pragma unroll
        for (int ni = 0; ni < 4; ++ni) {
            int c = bn + wn * 32 + ni * 8 + t * 2;
            if (c < Ncols) {
                float b0 = bias[c], b1 = bias[c + 1];
                if (r0 < M) {
                    float v0 = fmaxf(acc[mi][ni][0] + b0, 0.0f);
                    float v1 = fmaxf(acc[mi][ni][1] + b1, 0.0f);
                    *reinterpret_cast<float2*>(C + (size_t)r0 * ldC + c) = make_float2(v0, v1);
                }
                if (r1 < M) {
                    float v2 = fmaxf(acc[mi][ni][2] + b0, 0.0f);
                    float v3 = fmaxf(acc[mi][ni][3] + b1, 0.0f);
                    *reinterpret_cast<float2*>(C + (size_t)r1 * ldC + c) = make_float2(v2, v3);
                }
            }
        }
    }
}

// ---------------- launch ----------------
extern "C" void kernel_launch(void* const* d_in, const int* in_sizes, int n_in,
                              void* d_out, int out_size) {
    (void)in_sizes; (void)n_in; (void)out_size;
    const float* x  = (const float*)d_in[0];
    const int*   ei = (const int*)d_in[1];
    const float* W1 = (const float*)d_in[2];
    const float* b1 = (const float*)d_in[3];
    const float* W2 = (const float*)d_in[4];
    const float* b2 = (const float*)d_in[5];
    const float* W3 = (const float*)d_in[6];
    const float* b3 = (const float*)d_in[7];
    float* out = (float*)d_out;
    const int* src = ei;
    const int* dst = ei + NE;

    void* p;
    float *T1, *T2, *H1, *H2, *Wp1, *Wp2, *Wp3, *bp1, *bp2, *bp3;
    cudaGetSymbolAddress(&p, g_T1);  T1  = (float*)p;
    cudaGetSymbolAddress(&p, g_T2);  T2  = (float*)p;
    cudaGetSymbolAddress(&p, g_H1);  H1  = (float*)p;
    cudaGetSymbolAddress(&p, g_H2);  H2  = (float*)p;
    cudaGetSymbolAddress(&p, g_Wp1); Wp1 = (float*)p;
    cudaGetSymbolAddress(&p, g_Wp2); Wp2 = (float*)p;
    cudaGetSymbolAddress(&p, g_Wp3); Wp3 = (float*)p;
    cudaGetSymbolAddress(&p, g_bp1); bp1 = (float*)p;
    cudaGetSymbolAddress(&p, g_bp2); bp2 = (float*)p;
    cudaGetSymbolAddress(&p, g_bp3); bp3 = (float*)p;

    const int TB = 256;
    const int MB = (NN + 127) / 128;  // 782

    // --- CSR build (by dst) + degree normalization ---
    k_zero2<<<(NN + TB - 1) / TB, TB>>>();
    k_hist<<<(NE + TB - 1) / TB, TB>>>(src, dst);
    k_dis<<<(NN + TB - 1) / TB, TB>>>();
    k_scan_block<<<SCAN_NB, SCAN_T>>>();
    k_scan_sums<<<1, 32>>>();
    k_finalize<<<SCAN_NB, SCAN_T>>>();
    k_zero_deg<<<(NN + TB - 1) / TB, TB>>>();
    k_fill<<<(NE + TB - 1) / TB, TB>>>(src, dst);

    // --- pack weights/biases into padded layouts ---
    k_pack_w<<<(3 * 128 * 256  + TB - 1) / TB, TB>>>(W1, Wp1, 128, 250, 128, 256);
    k_pack_w<<<(3 * 256 * 512  + TB - 1) / TB, TB>>>(W2, Wp2, 250, 500, 256, 512);
    k_pack_w<<<(3 * 512 * 1024 + TB - 1) / TB, TB>>>(W3, Wp3, 500, 1000, 512, 1024);
    k_pack_b<<<1, 256>>>(b1, bp1, 250, 256);
    k_pack_b<<<2, 256>>>(b2, bp2, 500, 512);
    k_pack_b<<<4, 256>>>(b3, bp3, 1000, 1024);

    // --- layer 1: 128 -> 250 (pad 256) ---
    k_spmm<<<dim3(NN, 1), 128>>>(x, 128, T1, x, 0);
    k_spmm<<<dim3(NN, 1), 128>>>(T1, 128, T2, x, 1);
    gemm3_tf32<128><<<dim3(2, MB), 256>>>(x, T1, T2, Wp1, 256, bp1, H1, 256, 256, NN);

    // --- layer 2: 250 (pad 256) -> 500 (pad 512) ---
    k_spmm<<<dim3(NN, 2), 128>>>(H1, 256, T1, H1, 0);
    k_spmm<<<dim3(NN, 2), 128>>>(T1, 256, T2, H1, 1);
    gemm3_tf32<256><<<dim3(4, MB), 256>>>(H1, T1, T2, Wp2, 512, bp2, H2, 512, 512, NN);

    // --- layer 3: 500 (pad 512) -> 1000 (out, stride 1000) ---
    k_spmm<<<dim3(NN, 4), 128>>>(H2, 512, T1, H2, 0);
    k_spmm<<<dim3(NN, 4), 128>>>(T1, 512, T2, H2, 1);
    gemm3_tf32<512><<<dim3(8, MB), 256>>>(H2, T1, T2, Wp3, 1024, bp3, out, 1000, 1000, NN);
}